// round 1
// baseline (speedup 1.0000x reference)
#include <cuda_runtime.h>

// Scratch accumulators in device globals (no allocation allowed).
__device__ double g_iou_sum;
__device__ double g_mse_sum;
__device__ unsigned long long g_ninc;
__device__ unsigned long long g_ncorr;

__global__ void zero_acc_kernel() {
    g_iou_sum = 0.0;
    g_mse_sum = 0.0;
    g_ninc = 0ull;
    g_ncorr = 0ull;
}

__global__ __launch_bounds__(256) void iou_reduce_kernel(
    const float4* __restrict__ pr, const float4* __restrict__ gt, int n)
{
    float iou_sum = 0.0f;
    float mse_sum = 0.0f;
    unsigned int ninc = 0u;
    unsigned int ncorr = 0u;

    int stride = gridDim.x * blockDim.x;
    for (int i = blockIdx.x * blockDim.x + threadIdx.x; i < n; i += stride) {
        float4 p = __ldg(&pr[i]);
        float4 g = __ldg(&gt[i]);

        // gt corners (cx, cy, w, h -> xyxy)
        float xminT = g.x - g.z * 0.5f;
        float xmaxT = g.x + g.z * 0.5f;
        float yminT = g.y - g.w * 0.5f;
        float ymaxT = g.y + g.w * 0.5f;
        // pred corners clipped to [0,1]
        float xminP = fmaxf(p.x - p.z * 0.5f, 0.0f);
        float xmaxP = fminf(p.x + p.z * 0.5f, 1.0f);
        float yminP = fmaxf(p.y - p.w * 0.5f, 0.0f);
        float ymaxP = fminf(p.y + p.w * 0.5f, 1.0f);
        // overlap box
        float o0 = fmaxf(xminT, xminP);
        float o1 = fmaxf(yminT, yminP);
        float o2 = fminf(xmaxT, xmaxP);
        float o3 = fminf(ymaxT, ymaxP);

        bool incorrect = (o2 < o0) || (o3 < o1);
        if (incorrect) {
            float dx = p.x - g.x;
            float dy = p.y - g.y;
            float dz = p.z - g.z;
            float dw = p.w - g.w;
            mse_sum += dx * dx + dy * dy + dz * dz + dw * dw;
            ninc++;
        } else {
            float area_p = p.z * p.w;
            float area_g = g.z * g.w;
            float inter = (o2 - o0) * (o3 - o1);
            float iou = inter / (area_p + area_g - inter + 1e-7f);
            iou_sum += iou;
            ncorr++;
        }
    }

    // Warp reduction
    #pragma unroll
    for (int off = 16; off > 0; off >>= 1) {
        iou_sum += __shfl_down_sync(0xFFFFFFFFu, iou_sum, off);
        mse_sum += __shfl_down_sync(0xFFFFFFFFu, mse_sum, off);
        ninc    += __shfl_down_sync(0xFFFFFFFFu, ninc, off);
        ncorr   += __shfl_down_sync(0xFFFFFFFFu, ncorr, off);
    }

    if ((threadIdx.x & 31) == 0) {
        atomicAdd(&g_iou_sum, (double)iou_sum);
        atomicAdd(&g_mse_sum, (double)mse_sum);
        atomicAdd(&g_ninc, (unsigned long long)ninc);
        atomicAdd(&g_ncorr, (unsigned long long)ncorr);
    }
}

__global__ void finalize_kernel(float* __restrict__ out) {
    unsigned long long ninc = g_ninc;
    unsigned long long ncorr = g_ncorr;
    double mse_denom = (double)(ninc * 4ull > 0ull ? ninc * 4ull : 1ull);
    double corr_denom = (double)(ncorr > 0ull ? ncorr : 1ull);
    float mse_mean = (float)(g_mse_sum / mse_denom);
    float iou_mean = (float)(g_iou_sum / corr_denom);
    float res_full = iou_mean + (ninc > 0ull ? -mse_mean : 0.0f);
    out[0] = (ncorr > 0ull) ? res_full : -mse_mean;
}

extern "C" void kernel_launch(void* const* d_in, const int* in_sizes, int n_in,
                              void* d_out, int out_size) {
    const float4* pr = (const float4*)d_in[0];
    const float4* gt = (const float4*)d_in[1];
    float* out = (float*)d_out;
    int n = in_sizes[0] / 4;  // element count -> number of boxes

    zero_acc_kernel<<<1, 1>>>();
    iou_reduce_kernel<<<1184, 256>>>(pr, gt, n);
    finalize_kernel<<<1, 1>>>(out);
}

// round 2
// speedup vs baseline: 1.2113x; 1.2113x over previous
#include <cuda_runtime.h>

#define NBLOCKS 1184
#define NTHREADS 256

// Per-block partials (overwritten every call — no zeroing needed).
__device__ float        g_part_iou[NBLOCKS];
__device__ float        g_part_mse[NBLOCKS];
__device__ unsigned int g_part_ninc[NBLOCKS];
__device__ unsigned int g_part_ncorr[NBLOCKS];
// Completion counter; the last block resets it to 0 -> replay-safe.
__device__ unsigned int g_done_count = 0;

struct Acc {
    float iou, mse;
    unsigned int ninc, ncorr;
};

__device__ __forceinline__ void process_box(const float4 p, const float4 g, Acc& a)
{
    // gt corners (cx, cy, w, h -> xyxy)
    float xminT = g.x - g.z * 0.5f;
    float xmaxT = g.x + g.z * 0.5f;
    float yminT = g.y - g.w * 0.5f;
    float ymaxT = g.y + g.w * 0.5f;
    // pred corners clipped to [0,1]
    float xminP = fmaxf(p.x - p.z * 0.5f, 0.0f);
    float xmaxP = fminf(p.x + p.z * 0.5f, 1.0f);
    float yminP = fmaxf(p.y - p.w * 0.5f, 0.0f);
    float ymaxP = fminf(p.y + p.w * 0.5f, 1.0f);
    // overlap box
    float o0 = fmaxf(xminT, xminP);
    float o1 = fmaxf(yminT, yminP);
    float o2 = fminf(xmaxT, xmaxP);
    float o3 = fminf(ymaxT, ymaxP);

    bool incorrect = (o2 < o0) || (o3 < o1);
    if (incorrect) {
        float dx = p.x - g.x;
        float dy = p.y - g.y;
        float dz = p.z - g.z;
        float dw = p.w - g.w;
        a.mse += dx * dx + dy * dy + dz * dz + dw * dw;
        a.ninc++;
    } else {
        float area_p = p.z * p.w;
        float area_g = g.z * g.w;
        float inter  = (o2 - o0) * (o3 - o1);
        a.iou += inter / (area_p + area_g - inter + 1e-7f);
        a.ncorr++;
    }
}

__global__ __launch_bounds__(NTHREADS) void iou_fused_kernel(
    const float4* __restrict__ pr, const float4* __restrict__ gt,
    float* __restrict__ out, int n)
{
    Acc a = {0.0f, 0.0f, 0u, 0u};

    const int tid    = blockIdx.x * NTHREADS + threadIdx.x;
    const int stride = NBLOCKS * NTHREADS;

    int i = tid;
    // Unroll x4: 8 independent 128-bit loads in flight per trip.
    for (; i + 3 * stride < n; i += 4 * stride) {
        float4 p0 = __ldg(&pr[i]);
        float4 g0 = __ldg(&gt[i]);
        float4 p1 = __ldg(&pr[i + stride]);
        float4 g1 = __ldg(&gt[i + stride]);
        float4 p2 = __ldg(&pr[i + 2 * stride]);
        float4 g2 = __ldg(&gt[i + 2 * stride]);
        float4 p3 = __ldg(&pr[i + 3 * stride]);
        float4 g3 = __ldg(&gt[i + 3 * stride]);
        process_box(p0, g0, a);
        process_box(p1, g1, a);
        process_box(p2, g2, a);
        process_box(p3, g3, a);
    }
    for (; i < n; i += stride) {
        process_box(__ldg(&pr[i]), __ldg(&gt[i]), a);
    }

    // Intra-warp reduce
    #pragma unroll
    for (int off = 16; off > 0; off >>= 1) {
        a.iou   += __shfl_down_sync(0xFFFFFFFFu, a.iou, off);
        a.mse   += __shfl_down_sync(0xFFFFFFFFu, a.mse, off);
        a.ninc  += __shfl_down_sync(0xFFFFFFFFu, a.ninc, off);
        a.ncorr += __shfl_down_sync(0xFFFFFFFFu, a.ncorr, off);
    }

    // Inter-warp reduce via smem
    __shared__ float s_iou[NTHREADS / 32];
    __shared__ float s_mse[NTHREADS / 32];
    __shared__ unsigned int s_ninc[NTHREADS / 32];
    __shared__ unsigned int s_ncorr[NTHREADS / 32];
    const int lane = threadIdx.x & 31;
    const int warp = threadIdx.x >> 5;
    if (lane == 0) {
        s_iou[warp]   = a.iou;
        s_mse[warp]   = a.mse;
        s_ninc[warp]  = a.ninc;
        s_ncorr[warp] = a.ncorr;
    }
    __syncthreads();
    if (warp == 0) {
        const int nw = NTHREADS / 32;
        float iou = (lane < nw) ? s_iou[lane] : 0.0f;
        float mse = (lane < nw) ? s_mse[lane] : 0.0f;
        unsigned int ninc  = (lane < nw) ? s_ninc[lane]  : 0u;
        unsigned int ncorr = (lane < nw) ? s_ncorr[lane] : 0u;
        #pragma unroll
        for (int off = 4; off > 0; off >>= 1) {
            iou   += __shfl_down_sync(0xFFFFFFFFu, iou, off);
            mse   += __shfl_down_sync(0xFFFFFFFFu, mse, off);
            ninc  += __shfl_down_sync(0xFFFFFFFFu, ninc, off);
            ncorr += __shfl_down_sync(0xFFFFFFFFu, ncorr, off);
        }
        if (lane == 0) {
            g_part_iou[blockIdx.x]   = iou;
            g_part_mse[blockIdx.x]   = mse;
            g_part_ninc[blockIdx.x]  = ninc;
            g_part_ncorr[blockIdx.x] = ncorr;
        }
    }

    // Last-block-done finalization
    __shared__ bool is_last;
    if (threadIdx.x == 0) {
        __threadfence();
        unsigned int prev = atomicAdd(&g_done_count, 1u);
        is_last = (prev == (unsigned int)(gridDim.x - 1));
    }
    __syncthreads();
    if (!is_last) return;

    float iou = 0.0f, mse = 0.0f;
    unsigned long long ninc = 0ull, ncorr = 0ull;
    for (int j = threadIdx.x; j < NBLOCKS; j += NTHREADS) {
        iou   += g_part_iou[j];
        mse   += g_part_mse[j];
        ninc  += g_part_ninc[j];
        ncorr += g_part_ncorr[j];
    }
    #pragma unroll
    for (int off = 16; off > 0; off >>= 1) {
        iou   += __shfl_down_sync(0xFFFFFFFFu, iou, off);
        mse   += __shfl_down_sync(0xFFFFFFFFu, mse, off);
        ninc  += __shfl_down_sync(0xFFFFFFFFu, ninc, off);
        ncorr += __shfl_down_sync(0xFFFFFFFFu, ncorr, off);
    }
    __shared__ float f_iou[NTHREADS / 32];
    __shared__ float f_mse[NTHREADS / 32];
    __shared__ unsigned long long f_ninc[NTHREADS / 32];
    __shared__ unsigned long long f_ncorr[NTHREADS / 32];
    if (lane == 0) {
        f_iou[warp] = iou; f_mse[warp] = mse;
        f_ninc[warp] = ninc; f_ncorr[warp] = ncorr;
    }
    __syncthreads();
    if (threadIdx.x == 0) {
        const int nw = NTHREADS / 32;
        double diou = 0.0, dmse = 0.0;
        unsigned long long tninc = 0ull, tncorr = 0ull;
        for (int w = 0; w < nw; w++) {
            diou += (double)f_iou[w];
            dmse += (double)f_mse[w];
            tninc += f_ninc[w];
            tncorr += f_ncorr[w];
        }
        double mse_denom  = (double)(tninc * 4ull > 0ull ? tninc * 4ull : 1ull);
        double corr_denom = (double)(tncorr > 0ull ? tncorr : 1ull);
        float mse_mean = (float)(dmse / mse_denom);
        float iou_mean = (float)(diou / corr_denom);
        float res_full = iou_mean + (tninc > 0ull ? -mse_mean : 0.0f);
        out[0] = (tncorr > 0ull) ? res_full : -mse_mean;
        g_done_count = 0u;  // reset for next graph replay
    }
}

extern "C" void kernel_launch(void* const* d_in, const int* in_sizes, int n_in,
                              void* d_out, int out_size) {
    const float4* pr = (const float4*)d_in[0];
    const float4* gt = (const float4*)d_in[1];
    float* out = (float*)d_out;
    int n = in_sizes[0] / 4;  // floats -> boxes

    iou_fused_kernel<<<NBLOCKS, NTHREADS>>>(pr, gt, out, n);
}

// round 3
// speedup vs baseline: 1.3138x; 1.0846x over previous
#include <cuda_runtime.h>

#define NBLOCKS 740     // 5 CTAs/SM x 148 SMs -> exactly one wave
#define NTHREADS 256

// Per-block partials (overwritten every call — no zeroing needed).
__device__ float        g_part_iou[NBLOCKS];
__device__ float        g_part_mse[NBLOCKS];
__device__ unsigned int g_part_ninc[NBLOCKS];
__device__ unsigned int g_part_ncorr[NBLOCKS];
// Completion counter; the last block resets it to 0 -> replay-safe.
__device__ unsigned int g_done_count = 0;

struct Acc {
    float iou, mse;
    unsigned int ninc, ncorr;
};

__device__ __forceinline__ float4 ldcs4(const float4* p) {
    return __ldcs(p);   // streaming (evict-first): no reuse, don't pollute L2
}

__device__ __forceinline__ void process_box(const float4 p, const float4 g, Acc& a)
{
    // gt corners (cx, cy, w, h -> xyxy)
    float xminT = g.x - g.z * 0.5f;
    float xmaxT = g.x + g.z * 0.5f;
    float yminT = g.y - g.w * 0.5f;
    float ymaxT = g.y + g.w * 0.5f;
    // pred corners clipped to [0,1]
    float xminP = fmaxf(p.x - p.z * 0.5f, 0.0f);
    float xmaxP = fminf(p.x + p.z * 0.5f, 1.0f);
    float yminP = fmaxf(p.y - p.w * 0.5f, 0.0f);
    float ymaxP = fminf(p.y + p.w * 0.5f, 1.0f);
    // overlap box
    float o0 = fmaxf(xminT, xminP);
    float o1 = fmaxf(yminT, yminP);
    float o2 = fminf(xmaxT, xmaxP);
    float o3 = fminf(ymaxT, ymaxP);

    bool incorrect = (o2 < o0) || (o3 < o1);
    if (incorrect) {
        float dx = p.x - g.x;
        float dy = p.y - g.y;
        float dz = p.z - g.z;
        float dw = p.w - g.w;
        a.mse += dx * dx + dy * dy + dz * dz + dw * dw;
        a.ninc++;
    } else {
        float area_p = p.z * p.w;
        float area_g = g.z * g.w;
        float inter  = (o2 - o0) * (o3 - o1);
        a.iou += inter / (area_p + area_g - inter + 1e-7f);
        a.ncorr++;
    }
}

__global__ __launch_bounds__(NTHREADS, 5) void iou_fused_kernel(
    const float4* __restrict__ pr, const float4* __restrict__ gt,
    float* __restrict__ out, int n)
{
    Acc a = {0.0f, 0.0f, 0u, 0u};

    const int tid    = blockIdx.x * NTHREADS + threadIdx.x;
    const int stride = NBLOCKS * NTHREADS;

    int i = tid;
    // Unroll x4: 8 independent 128-bit loads in flight per trip.
    for (; i + 3 * stride < n; i += 4 * stride) {
        float4 p0 = ldcs4(&pr[i]);
        float4 g0 = ldcs4(&gt[i]);
        float4 p1 = ldcs4(&pr[i + stride]);
        float4 g1 = ldcs4(&gt[i + stride]);
        float4 p2 = ldcs4(&pr[i + 2 * stride]);
        float4 g2 = ldcs4(&gt[i + 2 * stride]);
        float4 p3 = ldcs4(&pr[i + 3 * stride]);
        float4 g3 = ldcs4(&gt[i + 3 * stride]);
        process_box(p0, g0, a);
        process_box(p1, g1, a);
        process_box(p2, g2, a);
        process_box(p3, g3, a);
    }
    for (; i < n; i += stride) {
        process_box(ldcs4(&pr[i]), ldcs4(&gt[i]), a);
    }

    // Intra-warp reduce
    #pragma unroll
    for (int off = 16; off > 0; off >>= 1) {
        a.iou   += __shfl_down_sync(0xFFFFFFFFu, a.iou, off);
        a.mse   += __shfl_down_sync(0xFFFFFFFFu, a.mse, off);
        a.ninc  += __shfl_down_sync(0xFFFFFFFFu, a.ninc, off);
        a.ncorr += __shfl_down_sync(0xFFFFFFFFu, a.ncorr, off);
    }

    // Inter-warp reduce via smem
    __shared__ float s_iou[NTHREADS / 32];
    __shared__ float s_mse[NTHREADS / 32];
    __shared__ unsigned int s_ninc[NTHREADS / 32];
    __shared__ unsigned int s_ncorr[NTHREADS / 32];
    const int lane = threadIdx.x & 31;
    const int warp = threadIdx.x >> 5;
    if (lane == 0) {
        s_iou[warp]   = a.iou;
        s_mse[warp]   = a.mse;
        s_ninc[warp]  = a.ninc;
        s_ncorr[warp] = a.ncorr;
    }
    __syncthreads();
    if (warp == 0) {
        const int nw = NTHREADS / 32;
        float iou = (lane < nw) ? s_iou[lane] : 0.0f;
        float mse = (lane < nw) ? s_mse[lane] : 0.0f;
        unsigned int ninc  = (lane < nw) ? s_ninc[lane]  : 0u;
        unsigned int ncorr = (lane < nw) ? s_ncorr[lane] : 0u;
        #pragma unroll
        for (int off = 4; off > 0; off >>= 1) {
            iou   += __shfl_down_sync(0xFFFFFFFFu, iou, off);
            mse   += __shfl_down_sync(0xFFFFFFFFu, mse, off);
            ninc  += __shfl_down_sync(0xFFFFFFFFu, ninc, off);
            ncorr += __shfl_down_sync(0xFFFFFFFFu, ncorr, off);
        }
        if (lane == 0) {
            g_part_iou[blockIdx.x]   = iou;
            g_part_mse[blockIdx.x]   = mse;
            g_part_ninc[blockIdx.x]  = ninc;
            g_part_ncorr[blockIdx.x] = ncorr;
        }
    }

    // Last-block-done finalization
    __shared__ bool is_last;
    if (threadIdx.x == 0) {
        __threadfence();
        unsigned int prev = atomicAdd(&g_done_count, 1u);
        is_last = (prev == (unsigned int)(gridDim.x - 1));
    }
    __syncthreads();
    if (!is_last) return;

    float iou = 0.0f, mse = 0.0f;
    unsigned long long ninc = 0ull, ncorr = 0ull;
    for (int j = threadIdx.x; j < NBLOCKS; j += NTHREADS) {
        iou   += g_part_iou[j];
        mse   += g_part_mse[j];
        ninc  += g_part_ninc[j];
        ncorr += g_part_ncorr[j];
    }
    #pragma unroll
    for (int off = 16; off > 0; off >>= 1) {
        iou   += __shfl_down_sync(0xFFFFFFFFu, iou, off);
        mse   += __shfl_down_sync(0xFFFFFFFFu, mse, off);
        ninc  += __shfl_down_sync(0xFFFFFFFFu, ninc, off);
        ncorr += __shfl_down_sync(0xFFFFFFFFu, ncorr, off);
    }
    __shared__ float f_iou[NTHREADS / 32];
    __shared__ float f_mse[NTHREADS / 32];
    __shared__ unsigned long long f_ninc[NTHREADS / 32];
    __shared__ unsigned long long f_ncorr[NTHREADS / 32];
    if (lane == 0) {
        f_iou[warp] = iou; f_mse[warp] = mse;
        f_ninc[warp] = ninc; f_ncorr[warp] = ncorr;
    }
    __syncthreads();
    if (threadIdx.x == 0) {
        const int nw = NTHREADS / 32;
        double diou = 0.0, dmse = 0.0;
        unsigned long long tninc = 0ull, tncorr = 0ull;
        for (int w = 0; w < nw; w++) {
            diou += (double)f_iou[w];
            dmse += (double)f_mse[w];
            tninc += f_ninc[w];
            tncorr += f_ncorr[w];
        }
        double mse_denom  = (double)(tninc * 4ull > 0ull ? tninc * 4ull : 1ull);
        double corr_denom = (double)(tncorr > 0ull ? tncorr : 1ull);
        float mse_mean = (float)(dmse / mse_denom);
        float iou_mean = (float)(diou / corr_denom);
        float res_full = iou_mean + (tninc > 0ull ? -mse_mean : 0.0f);
        out[0] = (tncorr > 0ull) ? res_full : -mse_mean;
        g_done_count = 0u;  // reset for next graph replay
    }
}

extern "C" void kernel_launch(void* const* d_in, const int* in_sizes, int n_in,
                              void* d_out, int out_size) {
    const float4* pr = (const float4*)d_in[0];
    const float4* gt = (const float4*)d_in[1];
    float* out = (float*)d_out;
    int n = in_sizes[0] / 4;  // floats -> boxes

    iou_fused_kernel<<<NBLOCKS, NTHREADS>>>(pr, gt, out, n);
}